// round 10
// baseline (speedup 1.0000x reference)
#include <cuda_runtime.h>

#define BATCH 8
#define H 8
#define L 1024
#define DK 64
#define BH 64            // BATCH*H
#define NPOS 65536       // BH*L
#define TTERMS 12
#define NT (TTERMS + 1)
#define CTX_ELEMS (BH * L * DK)   // 4194304

// -------- scratch (device globals; no runtime allocation) --------
__device__ float g_y[4][NPOS];
__device__ float2 g_part[4][H][BATCH][4];   // per-block BN partials (br, o, b, lquarter)
__device__ float g_Qm[NPOS];
__device__ float g_Km[NPOS];
__device__ float g_M[BH][NT * DK];       // final V-moments (incl 1/t!)
__device__ float g_Z[BH][NT];            // final Z-moments (incl 1/t!)
__device__ float g_cscale;

__constant__ float c_invfact[NT] = {
    1.0f, 1.0f, 0.5f, 1.0f / 6.0f, 1.0f / 24.0f, 1.0f / 120.0f,
    1.0f / 720.0f, 1.0f / 5040.0f, 1.0f / 40320.0f, 1.0f / 362880.0f,
    1.0f / 3628800.0f, 1.0f / 39916800.0f, 1.0f / 479001600.0f};

// -------- K12: fused projection + both conv branches + BN partials --------
// grid (b=8, side=2, lq=4); 1024 threads. side 0 = Q (branches 0,1), 1 = K (2,3).
// Each block: proj 8 h-rows over its 256-l range (+/-4 halo) into smem, then
// conv F=3 and F=9 for all 8 output channels, y writes + stats partials.
__global__ void __launch_bounds__(1024) k12_proj_conv(
    const float* __restrict__ Q, const float* __restrict__ K,
    const float* __restrict__ wq, const float* __restrict__ wk,
    const float* __restrict__ cq3w, const float* __restrict__ cq3b,
    const float* __restrict__ cq9w, const float* __restrict__ cq9b,
    const float* __restrict__ ck3w, const float* __restrict__ ck3b,
    const float* __restrict__ ck9w, const float* __restrict__ ck9b) {
    int b = blockIdx.x, side = blockIdx.y, lq = blockIdx.z;
    const float* src = side ? K : Q;
    const float* w = side ? wk : wq;
    const float* w3 = side ? ck3w : cq3w;
    const float* b3 = side ? ck3b : cq3b;
    const float* w9 = side ? ck9w : cq9w;
    const float* b9 = side ? ck9b : cq9b;

    __shared__ float sp[H][264];         // proj with halo (ll = l - (lq*256-4))
    __shared__ float sw3[H * H * 3];
    __shared__ float sw9[H * H * 9];
    __shared__ float ssum[16], ssq[16];
    int tid = threadIdx.x;
    if (tid < 192) sw3[tid] = __ldg(w3 + tid);
    if (tid >= 256 && tid < 256 + 576) sw9[tid - 256] = __ldg(w9 + (tid - 256));
    if (tid >= 960 && tid < 976) { ssum[tid - 960] = 0.0f; ssq[tid - 960] = 0.0f; }

    int l0 = lq * 256 - 4;
    for (int idx = tid; idx < H * 264; idx += 1024) {
        int h = idx / 264, ll = idx % 264;
        int l = l0 + ll;
        float s = 0.0f;
        if (l >= 0 && l < L) {
            const float4* p = (const float4*)(src + (((size_t)b * H + h) * L + l) * DK);
#pragma unroll
            for (int d4 = 0; d4 < 16; d4++) {
                float4 pv = p[d4];
                float4 wv = __ldg(((const float4*)w) + d4);
                s += pv.x * wv.x + pv.y * wv.y + pv.z * wv.z + pv.w * wv.w;
            }
        }
        sp[h][ll] = s;
    }
    __syncthreads();

    int lane = tid & 31;
#pragma unroll
    for (int k = 0; k < 4; k++) {
        int idx = k * 1024 + tid;
        int g = idx >> 8;          // 0..15 (uniform per warp)
        int o = g & 7, fs = g >> 3;
        int lloc = idx & 255;
        int ll = lloc + 4;         // center index into sp
        float acc;
        if (fs == 0) {
            acc = __ldg(b3 + o);
#pragma unroll
            for (int i = 0; i < H; i++)
#pragma unroll
                for (int f = 0; f < 3; f++)
                    acc += sw3[(o * H + i) * 3 + f] * sp[i][ll - 1 + f];
        } else {
            acc = __ldg(b9 + o);
#pragma unroll
            for (int i = 0; i < H; i++)
#pragma unroll
                for (int f = 0; f < 9; f++)
                    acc += sw9[(o * H + i) * 9 + f] * sp[i][ll - 4 + f];
        }
        int br = side * 2 + fs;
        g_y[br][b * (H * L) + o * L + lq * 256 + lloc] = acc;
        float s1 = acc, s2 = acc * acc;
#pragma unroll
        for (int off = 16; off; off >>= 1) {
            s1 += __shfl_down_sync(0xffffffffu, s1, off);
            s2 += __shfl_down_sync(0xffffffffu, s2, off);
        }
        if (lane == 0) { atomicAdd(&ssum[g], s1); atomicAdd(&ssq[g], s2); }
    }
    __syncthreads();
    if (tid < 16) {
        int o = tid & 7, fs = tid >> 3;
        g_part[side * 2 + fs][o][b][lq] = make_float2(ssum[tid], ssq[tid]);
    }
}

// -------- K45: fused BN-affine + softmax + cat/reshape-max + moments --------
// grid (r=32, half=2, qk=2); 1024 threads.
__global__ void __launch_bounds__(1024) k45_smmax_mom(
    const float* __restrict__ V,
    const float* __restrict__ wbq, const float* __restrict__ wbk,
    const float* __restrict__ g0, const float* __restrict__ be0,
    const float* __restrict__ g1, const float* __restrict__ be1,
    const float* __restrict__ g2, const float* __restrict__ be2,
    const float* __restrict__ g3, const float* __restrict__ be3) {
    int r = blockIdx.x, half = blockIdx.y, qk = blockIdx.z;
    int br = qk * 2 + half;
    int tid = threadIdx.x;
    int row01 = tid >> 9, j = tid & 511;
    int srcrow = 2 * r + row01;
    int o = srcrow & 7;

    // BN affine inline from partials
    const float* gg;
    const float* bb;
    if (br == 0) { gg = g0; bb = be0; }
    else if (br == 1) { gg = g1; bb = be1; }
    else if (br == 2) { gg = g2; bb = be2; }
    else { gg = g3; bb = be3; }
    float s1 = 0.0f, s2 = 0.0f;
#pragma unroll
    for (int b = 0; b < BATCH; b++)
#pragma unroll
        for (int lq = 0; lq < 4; lq++) {
            float2 p = g_part[br][o][b][lq];
            s1 += p.x;
            s2 += p.y;
        }
    float n = (float)(BATCH * L);
    float mu = s1 / n;
    float var = s2 / n - mu * mu;
    float sc = __ldg(gg + o) / sqrtf(var + 1e-5f);
    float sh = __ldg(bb + o) - mu * sc;

    const float2* y2 = (const float2*)&g_y[br][srcrow * L];
    float2 yv = y2[j];
    float v0 = yv.x * sc + sh;
    float v1 = yv.y * sc + sh;

    __shared__ float red[32];
    __shared__ float sKm[L];
    float m = fmaxf(v0, v1);
#pragma unroll
    for (int off = 16; off; off >>= 1) m = fmaxf(m, __shfl_xor_sync(0xffffffffu, m, off));
    int w = tid >> 5, ln = tid & 31;
    if (ln == 0) red[w] = m;
    __syncthreads();
    float mx = -1e30f;
#pragma unroll
    for (int i = 0; i < 16; i++) mx = fmaxf(mx, red[row01 * 16 + i]);
    __syncthreads();

    float e0 = __expf(v0 - mx), e1 = __expf(v1 - mx);
    float ss = e0 + e1;
#pragma unroll
    for (int off = 16; off; off >>= 1) ss += __shfl_xor_sync(0xffffffffu, ss, off);
    if (ln == 0) red[w] = ss;
    __syncthreads();
    float tot = 0.0f;
#pragma unroll
    for (int i = 0; i < 16; i++) tot += red[row01 * 16 + i];
    float val = fmaxf(e0, e1) / tot;

    int outrow = half * 32 + r;
    int outpos = row01 * 512 + j;
    float* dst = qk ? g_Km : g_Qm;
    dst[outrow * L + outpos] = val;

    if (qk == 0) {
        if (r == 0 && half == 0 && tid == 0) {
            float s = 0.0f;
            for (int d = 0; d < DK; d++) s += wbq[d] * wbk[d];
            g_cscale = s * 0.125f;  // 1/sqrt(64)
        }
        return;
    }

    // ---- moments for bh = outrow (Km row is in this block) ----
    sKm[outpos] = val;
    __syncthreads();

    int bh = outrow;
    int kg = tid >> 6, d = tid & 63;   // 16 k-groups x 64 d
    float acc[NT];
#pragma unroll
    for (int t = 0; t < NT; t++) acc[t] = 0.0f;
    const float* vb = V + (size_t)bh * L * DK;
    int kbase = kg * 64;
#pragma unroll 4
    for (int jj = 0; jj < 64; jj++) {
        int k = kbase + jj;
        float kv = sKm[k];
        float v = __ldg(vb + (size_t)k * DK + d);
        float kv2 = kv * kv;
        float pe = v, po = v * kv;
        acc[0] += pe;
        acc[1] += po;
#pragma unroll
        for (int t = 2; t < NT; t += 2) {
            pe *= kv2;
            acc[t] += pe;
            if (t + 1 < NT) {
                po *= kv2;
                acc[t + 1] += po;
            }
        }
    }
    __shared__ float mred[8][NT][DK];   // 26.6 KB
    __shared__ float zred[16][NT];
    if (kg >= 8) {
#pragma unroll
        for (int t = 0; t < NT; t++) mred[kg - 8][t][d] = acc[t];
    }
    // Z-moments: one lane per k-group accumulates sum_k Km^t
    if (d == 0) {
        float za[NT];
#pragma unroll
        for (int t = 0; t < NT; t++) za[t] = 0.0f;
        for (int jj = 0; jj < 64; jj++) {
            float kv = sKm[kbase + jj];
            float kv2 = kv * kv;
            float pe = 1.0f, po = kv;
            za[0] += pe;
            za[1] += po;
#pragma unroll
            for (int t = 2; t < NT; t += 2) {
                pe *= kv2;
                za[t] += pe;
                if (t + 1 < NT) {
                    po *= kv2;
                    za[t + 1] += po;
                }
            }
        }
#pragma unroll
        for (int t = 0; t < NT; t++) zred[kg][t] = za[t];
    }
    __syncthreads();
    if (kg < 8) {
#pragma unroll
        for (int t = 0; t < NT; t++) mred[kg][t][d] += acc[t];
    }
    __syncthreads();
    if (tid < NT * DK) {
        int t = tid >> 6, dd = tid & 63;
        float s = 0.0f;
#pragma unroll
        for (int g = 0; g < 8; g++) s += mred[g][t][dd];
        g_M[bh][t * DK + dd] = s * c_invfact[t];
    }
    if (tid < NT) {
        float s = 0.0f;
#pragma unroll
        for (int g = 0; g < 16; g++) s += zred[g][tid];
        g_Z[bh][tid] = s * c_invfact[tid];
    }
}

// -------- K6: analytic z, single-pass exp+scale+store, ctx via Horner --------
// grid (qc=8, bh=64); 256 threads = 8 warps; each warp 16 q rows (128 rows/block)
__global__ void __launch_bounds__(256) k6_main(float* __restrict__ out) {
    int bh = blockIdx.y;
    int tid = threadIdx.x;
    __shared__ float sKm[L];
    __shared__ float sM[NT * DK];
    __shared__ float sZ[NT];
    for (int i = tid; i < L; i += 256) sKm[i] = g_Km[bh * L + i];
    for (int i = tid; i < NT * DK; i += 256) sM[i] = g_M[bh][i];
    if (tid < NT) sZ[tid] = g_Z[bh][tid];
    __syncthreads();

    int wi = tid >> 5, lane = tid & 31;
    float cs = g_cscale;
    const float* qmrow = g_Qm + bh * L;

#pragma unroll 1
    for (int rr = 0; rr < 16; rr++) {
        int q = blockIdx.x * 128 + wi * 16 + rr;
        float a = __ldg(qmrow + q) * cs;

        // z = sum_k exp(a*Km_k) analytically (13-term Horner, scalar)
        float z = sZ[TTERMS];
#pragma unroll
        for (int t = TTERMS - 1; t >= 0; t--) z = z * a + sZ[t];
        float invz = 1.0f / z;

        float* attn = out + CTX_ELEMS + ((size_t)bh * L + q) * L;
#pragma unroll
        for (int j = 0; j < 8; j++) {
            float4 kmv = ((const float4*)sKm)[j * 32 + lane];
            float4 o4;
            o4.x = __expf(a * kmv.x) * invz;
            o4.y = __expf(a * kmv.y) * invz;
            o4.z = __expf(a * kmv.z) * invz;
            o4.w = __expf(a * kmv.w) * invz;
            __stcs(((float4*)attn) + j * 32 + lane, o4);
        }

        float* ctx = out + ((size_t)bh * L + q) * DK;
#pragma unroll
        for (int dd = 0; dd < 2; dd++) {
            int d = lane + dd * 32;
            float num = sM[TTERMS * DK + d];
#pragma unroll
            for (int t = TTERMS - 1; t >= 0; t--) num = num * a + sM[t * DK + d];
            ctx[d] = num * invz;
        }
    }
}

extern "C" void kernel_launch(void* const* d_in, const int* in_sizes, int n_in,
                              void* d_out, int out_size) {
    (void)in_sizes;
    (void)n_in;
    (void)out_size;
    const float* Q = (const float*)d_in[0];
    const float* K = (const float*)d_in[1];
    const float* V = (const float*)d_in[2];
    // d_in[3] = attn_mask (unused, faithful to reference)
    const float* wq = (const float*)d_in[4];
    const float* wk = (const float*)d_in[5];
    const float* wbq = (const float*)d_in[6];
    const float* wbk = (const float*)d_in[7];
    const float* cq3_w = (const float*)d_in[8];
    const float* cq3_b = (const float*)d_in[9];
    const float* cq9_w = (const float*)d_in[10];
    const float* cq9_b = (const float*)d_in[11];
    const float* ck3_w = (const float*)d_in[12];
    const float* ck3_b = (const float*)d_in[13];
    const float* ck9_w = (const float*)d_in[14];
    const float* ck9_b = (const float*)d_in[15];
    const float* bnq3_g = (const float*)d_in[16];
    const float* bnq3_b = (const float*)d_in[17];
    const float* bnq9_g = (const float*)d_in[18];
    const float* bnq9_b = (const float*)d_in[19];
    const float* bnk3_g = (const float*)d_in[20];
    const float* bnk3_b = (const float*)d_in[21];
    const float* bnk9_g = (const float*)d_in[22];
    const float* bnk9_b = (const float*)d_in[23];
    float* out = (float*)d_out;

    k12_proj_conv<<<dim3(8, 2, 4), 1024>>>(Q, K, wq, wk,
                                           cq3_w, cq3_b, cq9_w, cq9_b,
                                           ck3_w, ck3_b, ck9_w, ck9_b);
    k45_smmax_mom<<<dim3(32, 2, 2), 1024>>>(V, wbq, wbk,
                                            bnq3_g, bnq3_b, bnq9_g, bnq9_b,
                                            bnk3_g, bnk3_b, bnk9_g, bnk9_b);
    k6_main<<<dim3(8, BH), 256>>>(out);
}

// round 12
// speedup vs baseline: 1.0125x; 1.0125x over previous
#include <cuda_runtime.h>

#define BATCH 8
#define H 8
#define L 1024
#define DK 64
#define BH 64            // BATCH*H
#define NPOS 65536       // BH*L
#define TTERMS 12
#define NT (TTERMS + 1)
#define CTX_ELEMS (BH * L * DK)   // 4194304

// -------- scratch (device globals; no runtime allocation) --------
__device__ float g_Qp[NPOS];
__device__ float g_Kp[NPOS];
__device__ float g_y[4][NPOS];
__device__ float2 g_part[4][H][BATCH];   // per-block BN partials (no atomics)
__device__ float g_Qm[NPOS];
__device__ float g_Km[NPOS];
__device__ float g_M[BH][NT * DK];       // final V-moments (incl 1/t!)
__device__ float g_Z[BH][NT];            // final Z-moments (incl 1/t!)
__device__ float g_cscale;

__constant__ float c_invfact[NT] = {
    1.0f, 1.0f, 0.5f, 1.0f / 6.0f, 1.0f / 24.0f, 1.0f / 120.0f,
    1.0f / 720.0f, 1.0f / 5040.0f, 1.0f / 40320.0f, 1.0f / 362880.0f,
    1.0f / 3628800.0f, 1.0f / 39916800.0f, 1.0f / 479001600.0f};

// -------- K1: Qp = Q . wq, Kp = K . wk (16 lanes per row, float4) --------
__global__ void k1_proj(const float* __restrict__ Q, const float* __restrict__ K,
                        const float* __restrict__ wq, const float* __restrict__ wk) {
    int gtid = blockIdx.x * blockDim.x + threadIdx.x;
    int warp = gtid >> 5;
    int lane = threadIdx.x & 31;
    int row = warp * 2 + (lane >> 4);   // 2 rows per warp
    int l16 = lane & 15;
    const float* src;
    const float* w;
    float* dst;
    int i;
    if (row < NPOS) { src = Q; w = wq; dst = g_Qp; i = row; }
    else            { src = K; w = wk; dst = g_Kp; i = row - NPOS; }
    float4 p = ((const float4*)(src + (size_t)i * DK))[l16];
    float4 wv = __ldg(((const float4*)w) + l16);
    float s = p.x * wv.x + p.y * wv.y + p.z * wv.z + p.w * wv.w;
#pragma unroll
    for (int off = 8; off; off >>= 1) s += __shfl_down_sync(0xffffffffu, s, off, 16);
    if (l16 == 0) dst[i] = s;
}

// -------- K2: all 4 Conv1d branches, smem-staged input, per-block BN partials --------
// 512 threads; each thread 2 outputs over full L.
template <int F>
__device__ __forceinline__ void conv_body(const float* __restrict__ x,
                                          const float* __restrict__ cw,
                                          const float* __restrict__ cb,
                                          int o, int b, int br) {
    const int pad = F / 2;
    __shared__ float wsh[H * F];
    __shared__ float sx[H][1032];   // ll = l + 4, zero-padded halo
    int tid = threadIdx.x;
    if (tid < H * F) wsh[tid] = __ldg(cw + o * (H * F) + tid);
    const float* xb = x + b * (H * L);
    for (int idx = tid; idx < H * 1032; idx += 512) {
        int h = idx >> 10;            // idx / 1032 approximated below — use exact:
        h = idx / 1032;
        int ll = idx - h * 1032;
        int l = ll - 4;
        sx[h][ll] = (l >= 0 && l < L) ? __ldg(xb + h * L + l) : 0.0f;
    }
    __syncthreads();

    int l0 = tid * 2;
    float bias = __ldg(cb + o);
    float acc[2];
    acc[0] = bias;
    acc[1] = bias;
#pragma unroll
    for (int i = 0; i < H; i++) {
        float xr[2 + F - 1];
#pragma unroll
        for (int m = 0; m < 2 + F - 1; m++) xr[m] = sx[i][l0 + m + 4 - pad];
#pragma unroll
        for (int f = 0; f < F; f++) {
            float wv = wsh[i * F + f];
            acc[0] += xr[f] * wv;
            acc[1] += xr[f + 1] * wv;
        }
    }

    float s1 = acc[0] + acc[1];
    float s2 = acc[0] * acc[0] + acc[1] * acc[1];
    ((float2*)&g_y[br][b * (H * L) + o * L])[tid] = make_float2(acc[0], acc[1]);
#pragma unroll
    for (int off = 16; off; off >>= 1) {
        s1 += __shfl_down_sync(0xffffffffu, s1, off);
        s2 += __shfl_down_sync(0xffffffffu, s2, off);
    }
    __shared__ float red1[16], red2[16];
    int wi = tid >> 5, ln = tid & 31;
    if (ln == 0) { red1[wi] = s1; red2[wi] = s2; }
    __syncthreads();
    if (tid == 0) {
        float t1 = 0.0f, t2 = 0.0f;
#pragma unroll
        for (int i = 0; i < 16; i++) { t1 += red1[i]; t2 += red2[i]; }
        g_part[br][o][b] = make_float2(t1, t2);
    }
}

__global__ void __launch_bounds__(512) k2_conv_all(
    const float* __restrict__ cq3w, const float* __restrict__ cq3b,
    const float* __restrict__ cq9w, const float* __restrict__ cq9b,
    const float* __restrict__ ck3w, const float* __restrict__ ck3b,
    const float* __restrict__ ck9w, const float* __restrict__ ck9b) {
    int o = blockIdx.x, b = blockIdx.y, br = blockIdx.z;
    const float* x = (br < 2) ? g_Qp : g_Kp;
    switch (br) {
        case 0: conv_body<3>(x, cq3w, cq3b, o, b, 0); break;
        case 1: conv_body<9>(x, cq9w, cq9b, o, b, 1); break;
        case 2: conv_body<3>(x, ck3w, ck3b, o, b, 2); break;
        default: conv_body<9>(x, ck9w, ck9b, o, b, 3); break;
    }
}

// -------- K45: fused BN-affine + softmax + cat/reshape-max + moments --------
// grid (r=32, half=2, qk=2); 1024 threads.
__global__ void __launch_bounds__(1024) k45_smmax_mom(
    const float* __restrict__ V,
    const float* __restrict__ wbq, const float* __restrict__ wbk,
    const float* __restrict__ g0, const float* __restrict__ be0,
    const float* __restrict__ g1, const float* __restrict__ be1,
    const float* __restrict__ g2, const float* __restrict__ be2,
    const float* __restrict__ g3, const float* __restrict__ be3) {
    int r = blockIdx.x, half = blockIdx.y, qk = blockIdx.z;
    int br = qk * 2 + half;
    int tid = threadIdx.x;
    int row01 = tid >> 9, j = tid & 511;
    int srcrow = 2 * r + row01;
    int o = srcrow & 7;

    // BN affine inline from partials
    const float* gg;
    const float* bb;
    if (br == 0) { gg = g0; bb = be0; }
    else if (br == 1) { gg = g1; bb = be1; }
    else if (br == 2) { gg = g2; bb = be2; }
    else { gg = g3; bb = be3; }
    float s1 = 0.0f, s2 = 0.0f;
#pragma unroll
    for (int b = 0; b < BATCH; b++) {
        float2 p = g_part[br][o][b];
        s1 += p.x;
        s2 += p.y;
    }
    float n = (float)(BATCH * L);
    float mu = s1 / n;
    float var = s2 / n - mu * mu;
    float sc = __ldg(gg + o) / sqrtf(var + 1e-5f);
    float sh = __ldg(bb + o) - mu * sc;

    const float2* y2 = (const float2*)&g_y[br][srcrow * L];
    float2 yv = y2[j];
    float v0 = yv.x * sc + sh;
    float v1 = yv.y * sc + sh;

    __shared__ float red[32];
    __shared__ float sKm[L];
    float m = fmaxf(v0, v1);
#pragma unroll
    for (int off = 16; off; off >>= 1) m = fmaxf(m, __shfl_xor_sync(0xffffffffu, m, off));
    int w = tid >> 5, ln = tid & 31;
    if (ln == 0) red[w] = m;
    __syncthreads();
    float mx = -1e30f;
#pragma unroll
    for (int i = 0; i < 16; i++) mx = fmaxf(mx, red[row01 * 16 + i]);
    __syncthreads();

    float e0 = __expf(v0 - mx), e1 = __expf(v1 - mx);
    float ss = e0 + e1;
#pragma unroll
    for (int off = 16; off; off >>= 1) ss += __shfl_xor_sync(0xffffffffu, ss, off);
    if (ln == 0) red[w] = ss;
    __syncthreads();
    float tot = 0.0f;
#pragma unroll
    for (int i = 0; i < 16; i++) tot += red[row01 * 16 + i];
    float val = fmaxf(e0, e1) / tot;

    int outrow = half * 32 + r;
    int outpos = row01 * 512 + j;
    float* dst = qk ? g_Km : g_Qm;
    dst[outrow * L + outpos] = val;

    if (qk == 0) {
        if (r == 0 && half == 0 && tid == 0) {
            float s = 0.0f;
            for (int d = 0; d < DK; d++) s += wbq[d] * wbk[d];
            g_cscale = s * 0.125f;  // 1/sqrt(64)
        }
        return;
    }

    // ---- moments for bh = outrow (Km row is in this block) ----
    sKm[outpos] = val;
    __syncthreads();

    int bh = outrow;
    int kg = tid >> 6, d = tid & 63;   // 16 k-groups x 64 d
    float acc[NT];
#pragma unroll
    for (int t = 0; t < NT; t++) acc[t] = 0.0f;
    const float* vb = V + (size_t)bh * L * DK;
    int kbase = kg * 64;
#pragma unroll 8
    for (int jj = 0; jj < 64; jj++) {
        int k = kbase + jj;
        float kv = sKm[k];
        float v = __ldg(vb + (size_t)k * DK + d);
        float kv2 = kv * kv;
        float pe = v, po = v * kv;
        acc[0] += pe;
        acc[1] += po;
#pragma unroll
        for (int t = 2; t < NT; t += 2) {
            pe *= kv2;
            acc[t] += pe;
            if (t + 1 < NT) {
                po *= kv2;
                acc[t + 1] += po;
            }
        }
    }
    __shared__ float mred[8][NT][DK];   // 26.6 KB
    __shared__ float zred[16][NT];
    if (kg >= 8) {
#pragma unroll
        for (int t = 0; t < NT; t++) mred[kg - 8][t][d] = acc[t];
    }
    // Z-moments: one lane per k-group accumulates sum_k Km^t
    if (d == 0) {
        float za[NT];
#pragma unroll
        for (int t = 0; t < NT; t++) za[t] = 0.0f;
#pragma unroll 8
        for (int jj = 0; jj < 64; jj++) {
            float kv = sKm[kbase + jj];
            float kv2 = kv * kv;
            float pe = 1.0f, po = kv;
            za[0] += pe;
            za[1] += po;
#pragma unroll
            for (int t = 2; t < NT; t += 2) {
                pe *= kv2;
                za[t] += pe;
                if (t + 1 < NT) {
                    po *= kv2;
                    za[t + 1] += po;
                }
            }
        }
#pragma unroll
        for (int t = 0; t < NT; t++) zred[kg][t] = za[t];
    }
    __syncthreads();
    if (kg < 8) {
#pragma unroll
        for (int t = 0; t < NT; t++) mred[kg][t][d] += acc[t];
    }
    __syncthreads();
    if (tid < NT * DK) {
        int t = tid >> 6, dd = tid & 63;
        float s = 0.0f;
#pragma unroll
        for (int g = 0; g < 8; g++) s += mred[g][t][dd];
        g_M[bh][t * DK + dd] = s * c_invfact[t];
    }
    if (tid < NT) {
        float s = 0.0f;
#pragma unroll
        for (int g = 0; g < 16; g++) s += zred[g][tid];
        g_Z[bh][tid] = s * c_invfact[tid];
    }
}

// -------- K6: analytic z, single-pass exp+scale+store, ctx via Horner --------
// grid (qc=16, bh=64); 256 threads = 8 warps; each warp 8 q rows (64 rows/block)
__global__ void __launch_bounds__(256) k6_main(float* __restrict__ out) {
    int bh = blockIdx.y;
    int tid = threadIdx.x;
    __shared__ float sKm[L];
    __shared__ float sM[NT * DK];
    __shared__ float sZ[NT];
    for (int i = tid; i < L; i += 256) sKm[i] = g_Km[bh * L + i];
    for (int i = tid; i < NT * DK; i += 256) sM[i] = g_M[bh][i];
    if (tid < NT) sZ[tid] = g_Z[bh][tid];
    __syncthreads();

    int wi = tid >> 5, lane = tid & 31;
    float cs = g_cscale;
    const float* qmrow = g_Qm + bh * L;

#pragma unroll 1
    for (int rr = 0; rr < 8; rr++) {
        int q = blockIdx.x * 64 + wi * 8 + rr;
        float a = __ldg(qmrow + q) * cs;

        // z = sum_k exp(a*Km_k) analytically (13-term Horner, scalar)
        float z = sZ[TTERMS];
#pragma unroll
        for (int t = TTERMS - 1; t >= 0; t--) z = z * a + sZ[t];
        float invz = 1.0f / z;

        float* attn = out + CTX_ELEMS + ((size_t)bh * L + q) * L;
#pragma unroll
        for (int j = 0; j < 8; j++) {
            float4 kmv = ((const float4*)sKm)[j * 32 + lane];
            float4 o4;
            o4.x = __expf(a * kmv.x) * invz;
            o4.y = __expf(a * kmv.y) * invz;
            o4.z = __expf(a * kmv.z) * invz;
            o4.w = __expf(a * kmv.w) * invz;
            __stcs(((float4*)attn) + j * 32 + lane, o4);
        }

        float* ctx = out + ((size_t)bh * L + q) * DK;
#pragma unroll
        for (int dd = 0; dd < 2; dd++) {
            int d = lane + dd * 32;
            float num = sM[TTERMS * DK + d];
#pragma unroll
            for (int t = TTERMS - 1; t >= 0; t--) num = num * a + sM[t * DK + d];
            ctx[d] = num * invz;
        }
    }
}

extern "C" void kernel_launch(void* const* d_in, const int* in_sizes, int n_in,
                              void* d_out, int out_size) {
    (void)in_sizes;
    (void)n_in;
    (void)out_size;
    const float* Q = (const float*)d_in[0];
    const float* K = (const float*)d_in[1];
    const float* V = (const float*)d_in[2];
    // d_in[3] = attn_mask (unused, faithful to reference)
    const float* wq = (const float*)d_in[4];
    const float* wk = (const float*)d_in[5];
    const float* wbq = (const float*)d_in[6];
    const float* wbk = (const float*)d_in[7];
    const float* cq3_w = (const float*)d_in[8];
    const float* cq3_b = (const float*)d_in[9];
    const float* cq9_w = (const float*)d_in[10];
    const float* cq9_b = (const float*)d_in[11];
    const float* ck3_w = (const float*)d_in[12];
    const float* ck3_b = (const float*)d_in[13];
    const float* ck9_w = (const float*)d_in[14];
    const float* ck9_b = (const float*)d_in[15];
    const float* bnq3_g = (const float*)d_in[16];
    const float* bnq3_b = (const float*)d_in[17];
    const float* bnq9_g = (const float*)d_in[18];
    const float* bnq9_b = (const float*)d_in[19];
    const float* bnk3_g = (const float*)d_in[20];
    const float* bnk3_b = (const float*)d_in[21];
    const float* bnk9_g = (const float*)d_in[22];
    const float* bnk9_b = (const float*)d_in[23];
    float* out = (float*)d_out;

    // 2*NPOS rows, 16 rows per block (8 warps x 2 rows)
    k1_proj<<<(2 * NPOS) / 16, 256>>>(Q, K, wq, wk);
    k2_conv_all<<<dim3(8, 8, 4), 512>>>(cq3_w, cq3_b, cq9_w, cq9_b,
                                        ck3_w, ck3_b, ck9_w, ck9_b);
    k45_smmax_mom<<<dim3(32, 2, 2), 1024>>>(V, wbq, wbk,
                                            bnq3_g, bnq3_b, bnq9_g, bnq9_b,
                                            bnk3_g, bnk3_b, bnk9_g, bnk9_b);
    k6_main<<<dim3(16, BH), 256>>>(out);
}